// round 16
// baseline (speedup 1.0000x reference)
#include <cuda_runtime.h>
#include <cuda_bf16.h>
#include <math.h>
#include <float.h>
#include <stdint.h>

#define KDIM 7168
#define NEXP 256
#define NGRP 8
#define GSIZE 32
#define TOPKN 8
#define TOPG 4
#define TTOT 8192
#define BSZ 2
#define SEQ 4096

#define EPS_DIRTY 3.0e-5f
#define RT_TOK 5
#define KC 32

// Scratch (no cudaMalloc allowed)
__device__ float g_logits[(size_t)TTOT * NEXP];   // 8 MB (approx, bf16x3)
__device__ float g_counts[BSZ * NEXP];
__device__ float g_ssum[BSZ * NEXP];
__device__ int   g_dirty[TTOT];
__device__ int   g_ndirty;

// ---------------------------------------------------------------------------
// XLA-style logistic: sigmoid(x) = 0.5 + 0.5 * tanh_xla(0.5 * x).
// ---------------------------------------------------------------------------
__device__ __forceinline__ float xla_sigmoid(float x) {
    float t  = __fmul_rn(0.5f, x);
    float tc = fminf(fmaxf(t, -7.90531110763549805f), 7.90531110763549805f);
    float x2 = __fmul_rn(tc, tc);
    float p = -2.76076847742355e-16f;
    p = __fadd_rn(__fmul_rn(p, x2),  2.00018790482477e-13f);
    p = __fadd_rn(__fmul_rn(p, x2), -8.60467152213735e-11f);
    p = __fadd_rn(__fmul_rn(p, x2),  5.12229709037114e-08f);
    p = __fadd_rn(__fmul_rn(p, x2),  1.48572235717979e-05f);
    p = __fadd_rn(__fmul_rn(p, x2),  6.37261928875436e-04f);
    p = __fadd_rn(__fmul_rn(p, x2),  4.89352455891786e-03f);
    p = __fmul_rn(p, tc);
    float q = 1.19825839466702e-06f;
    q = __fadd_rn(__fmul_rn(q, x2), 1.18534705686654e-04f);
    q = __fadd_rn(__fmul_rn(q, x2), 2.26843463243900e-03f);
    q = __fadd_rn(__fmul_rn(q, x2), 4.89352518554385e-03f);
    float th = __fdiv_rn(p, q);
    th = (fabsf(t) < 0.0004f) ? t : th;
    return __fadd_rn(0.5f, __fmul_rn(0.5f, th));
}

__global__ void zero_kernel() {
    int i = threadIdx.x;
    if (i < BSZ * NEXP) { g_counts[i] = 0.0f; g_ssum[i] = 0.0f; }
    if (i == 0) g_ndirty = 0;
}

// ---------------------------------------------------------------------------
// bf16 helpers
// ---------------------------------------------------------------------------
__device__ __forceinline__ void bsplit2(float x0, float x1,
                                        uint32_t& h, uint32_t& l) {
    __nv_bfloat16 h0 = __float2bfloat16_rn(x0);
    __nv_bfloat16 h1 = __float2bfloat16_rn(x1);
    h = ((uint32_t)__bfloat16_as_ushort(h1) << 16) | __bfloat16_as_ushort(h0);
    __nv_bfloat16 l0 = __float2bfloat16_rn(x0 - __bfloat162float(h0));
    __nv_bfloat16 l1 = __float2bfloat16_rn(x1 - __bfloat162float(h1));
    l = ((uint32_t)__bfloat16_as_ushort(l1) << 16) | __bfloat16_as_ushort(l0);
}
__device__ __forceinline__ void mmabf(float* c, const uint32_t* a, const uint32_t* b) {
    asm volatile(
        "mma.sync.aligned.m16n8k16.row.col.f32.bf16.bf16.f32 "
        "{%0,%1,%2,%3}, {%4,%5,%6,%7}, {%8,%9}, {%0,%1,%2,%3};"
        : "+f"(c[0]), "+f"(c[1]), "+f"(c[2]), "+f"(c[3])
        : "r"(a[0]), "r"(a[1]), "r"(a[2]), "r"(a[3]), "r"(b[0]), "r"(b[1]));
}
__device__ __forceinline__ uint32_t cvta_smem(const void* p) {
    uint32_t a;
    asm("{ .reg .u64 t; cvta.to.shared.u64 t, %1; cvt.u32.u64 %0, t; }"
        : "=r"(a) : "l"(p));
    return a;
}
__device__ __forceinline__ void ldm4(uint32_t& r0, uint32_t& r1,
                                     uint32_t& r2, uint32_t& r3, uint32_t a) {
    asm volatile("ldmatrix.sync.aligned.m8n8.x4.shared.b16 {%0,%1,%2,%3}, [%4];"
                 : "=r"(r0), "=r"(r1), "=r"(r2), "=r"(r3) : "r"(a));
}

// ---------------------------------------------------------------------------
// Approx GEMM: logits = x @ w^T via 3-pass bf16 split (hh + lh + hl).
// BM=BN=128, BK=32, 256 threads, warps 4(m) x 2(n), warp tile 32x64.
// Fragments loaded with ldmatrix.x4 — lane mappings reproduce the exact
// registers of the (passing) scalar-LDS version bit-for-bit.
// ---------------------------------------------------------------------------
__global__ __launch_bounds__(256) void gemm_bf16(const float* __restrict__ A,
                                                 const float* __restrict__ B) {
    __shared__ uint32_t Ah[128][20], Al[128][20];
    __shared__ uint32_t Bh[128][20], Bl[128][20];

    const int tid = threadIdx.x;
    const int l = tid & 31;
    const int wid = tid >> 5;
    const int warpm = wid & 3, warpn = wid >> 2;
    const int m0 = warpm * 32, n0 = warpn * 64;
    const int t0 = blockIdx.y * 128, e0 = blockIdx.x * 128;

    const int lm = tid >> 1;            // 0..127 (row)
    const int lhalf = (tid & 1) * 16;   // float offset within 32-k chunk
    const float* Aptr = A + (size_t)(t0 + lm) * KDIM + lhalf;
    const float* Bptr = B + (size_t)(e0 + lm) * KDIM + lhalf;

    float acc[2][8][4];
#pragma unroll
    for (int i = 0; i < 2; i++)
#pragma unroll
        for (int j = 0; j < 8; j++)
#pragma unroll
            for (int v = 0; v < 4; v++) acc[i][j][v] = 0.0f;

    float4 av[4], bv[4];
#pragma unroll
    for (int q = 0; q < 4; q++) {
        av[q] = *(const float4*)(Aptr + q * 4);
        bv[q] = *(const float4*)(Bptr + q * 4);
    }

    const int jbase = (tid & 1) * 8;
    const int g  = l >> 3;        // ldmatrix lane group 0..3
    const int r8 = l & 7;
    const uint32_t ah_base = cvta_smem(&Ah[0][0]);
    const uint32_t al_base = cvta_smem(&Al[0][0]);
    const uint32_t bh_base = cvta_smem(&Bh[0][0]);
    const uint32_t bl_base = cvta_smem(&Bl[0][0]);

    for (int k0 = 0; k0 < KDIM; k0 += 32) {
        __syncthreads();
#pragma unroll
        for (int q = 0; q < 4; q++) {
            uint32_t h, lo;
            bsplit2(av[q].x, av[q].y, h, lo);
            Ah[lm][jbase + q * 2] = h;     Al[lm][jbase + q * 2] = lo;
            bsplit2(av[q].z, av[q].w, h, lo);
            Ah[lm][jbase + q * 2 + 1] = h; Al[lm][jbase + q * 2 + 1] = lo;
            bsplit2(bv[q].x, bv[q].y, h, lo);
            Bh[lm][jbase + q * 2] = h;     Bl[lm][jbase + q * 2] = lo;
            bsplit2(bv[q].z, bv[q].w, h, lo);
            Bh[lm][jbase + q * 2 + 1] = h; Bl[lm][jbase + q * 2 + 1] = lo;
        }
        __syncthreads();
        if (k0 + 32 < KDIM) {
#pragma unroll
            for (int q = 0; q < 4; q++) {
                av[q] = *(const float4*)(Aptr + k0 + 32 + q * 4);
                bv[q] = *(const float4*)(Bptr + k0 + 32 + q * 4);
            }
        }

#pragma unroll
        for (int kb = 0; kb < 2; kb++) {
            const int joff = kb * 8;
            uint32_t afh[2][4], afl[2][4], bf[8][2];
            // A fragments: matrix g -> row +(g&1)*8, kword +(g>>1)*4
#pragma unroll
            for (int mt = 0; mt < 2; mt++) {
                int arow = m0 + mt * 16 + r8 + (g & 1) * 8;
                int awrd = joff + (g >> 1) * 4;
                uint32_t off = (uint32_t)(arow * 20 + awrd) * 4u;
                ldm4(afh[mt][0], afh[mt][1], afh[mt][2], afh[mt][3], ah_base + off);
                ldm4(afl[mt][0], afl[mt][1], afl[mt][2], afl[mt][3], al_base + off);
            }
            // B-hi fragments: pair p covers nt=2p,2p+1; matrix g -> nt +(g>>1), kword +(g&1)*4
#pragma unroll
            for (int p = 0; p < 4; p++) {
                int brow = n0 + (p * 2 + (g >> 1)) * 8 + r8;
                int bwrd = joff + (g & 1) * 4;
                uint32_t off = (uint32_t)(brow * 20 + bwrd) * 4u;
                ldm4(bf[p * 2][0], bf[p * 2][1], bf[p * 2 + 1][0], bf[p * 2 + 1][1],
                     bh_base + off);
            }
#pragma unroll
            for (int mt = 0; mt < 2; mt++)
#pragma unroll
                for (int nt = 0; nt < 8; nt++) mmabf(acc[mt][nt], afh[mt], bf[nt]);
#pragma unroll
            for (int mt = 0; mt < 2; mt++)
#pragma unroll
                for (int nt = 0; nt < 8; nt++) mmabf(acc[mt][nt], afl[mt], bf[nt]);
            // B-lo fragments
#pragma unroll
            for (int p = 0; p < 4; p++) {
                int brow = n0 + (p * 2 + (g >> 1)) * 8 + r8;
                int bwrd = joff + (g & 1) * 4;
                uint32_t off = (uint32_t)(brow * 20 + bwrd) * 4u;
                ldm4(bf[p * 2][0], bf[p * 2][1], bf[p * 2 + 1][0], bf[p * 2 + 1][1],
                     bl_base + off);
            }
#pragma unroll
            for (int mt = 0; mt < 2; mt++)
#pragma unroll
                for (int nt = 0; nt < 8; nt++) mmabf(acc[mt][nt], afh[mt], bf[nt]);
        }
    }

    const int r = l >> 2, c = l & 3;
#pragma unroll
    for (int mt = 0; mt < 2; mt++)
#pragma unroll
        for (int nt = 0; nt < 8; nt++) {
            int row = t0 + m0 + mt * 16 + r;
            int col = e0 + n0 + nt * 8 + 2 * c;
            *(float2*)&g_logits[(size_t)row * NEXP + col] =
                make_float2(acc[mt][nt][0], acc[mt][nt][1]);
            *(float2*)&g_logits[(size_t)(row + 8) * NEXP + col] =
                make_float2(acc[mt][nt][2], acc[mt][nt][3]);
        }
}

// ---------------------------------------------------------------------------
// Approx routing + dirty detection (validated r11-r15).
// ---------------------------------------------------------------------------
__global__ __launch_bounds__(256) void route_approx(const float* __restrict__ bias,
                                                    float* __restrict__ out) {
    const unsigned FULL = 0xffffffffu;
    int warp = (blockIdx.x * blockDim.x + threadIdx.x) >> 5;
    int l = threadIdx.x & 31;
    if (warp >= TTOT) return;
    const int t = warp;
    const float* lgp = g_logits + (size_t)t * NEXP;

    float orig[NGRP], val[NGRP], gscore[NGRP];
#pragma unroll
    for (int j = 0; j < NGRP; j++) {
        float s = xla_sigmoid(lgp[j * GSIZE + l]);
        orig[j] = s;
        val[j] = __fadd_rn(s, bias[j * GSIZE + l]);
    }

#pragma unroll
    for (int j = 0; j < NGRP; j++) {
        float m1 = val[j], m2 = -FLT_MAX;
#pragma unroll
        for (int off = 16; off > 0; off >>= 1) {
            float o1 = __shfl_xor_sync(FULL, m1, off);
            float o2 = __shfl_xor_sync(FULL, m2, off);
            float hi = fmaxf(m1, o1);
            float lo = fminf(m1, o1);
            m2 = fmaxf(fmaxf(m2, o2), lo);
            m1 = hi;
        }
        gscore[j] = __fadd_rn(m1, m2);
    }

    unsigned gsel = 0; float g4 = 0.0f;
    for (int rr = 0; rr < TOPG; rr++) {
        float best = -FLT_MAX; int bi = 0;
#pragma unroll
        for (int j = 0; j < NGRP; j++)
            if (!((gsel >> j) & 1u) && gscore[j] > best) { best = gscore[j]; bi = j; }
        gsel |= 1u << bi;
        g4 = best;
    }
    float g5 = -FLT_MAX;
#pragma unroll
    for (int j = 0; j < NGRP; j++)
        if (!((gsel >> j) & 1u)) g5 = fmaxf(g5, gscore[j]);
    bool dirty = (g4 - g5) < EPS_DIRTY;

#pragma unroll
    for (int j = 0; j < NGRP; j++)
        if (!((gsel >> j) & 1u)) val[j] = -FLT_MAX;

    float wsel[TOPKN]; int isel[TOPKN];
    float prev = 1e30f;
#pragma unroll
    for (int rr = 0; rr < TOPKN; rr++) {
        float bv = -FLT_MAX; int bj = 0;
#pragma unroll
        for (int j = 0; j < NGRP; j++)
            if (val[j] > bv) { bv = val[j]; bj = j; }
        int be = bj * GSIZE + l;
#pragma unroll
        for (int off = 16; off > 0; off >>= 1) {
            float ov = __shfl_xor_sync(FULL, bv, off);
            int   oe = __shfl_xor_sync(FULL, be, off);
            if (ov > bv || (ov == bv && oe < be)) { bv = ov; be = oe; }
        }
        dirty |= (prev - bv) < EPS_DIRTY;
        prev = bv;
        int jw = be >> 5, lw = be & 31;
        float cand = 0.0f;
#pragma unroll
        for (int j = 0; j < NGRP; j++) if (j == jw) cand = orig[j];
        float w = __shfl_sync(FULL, cand, lw);
        if (l == lw) {
#pragma unroll
            for (int j = 0; j < NGRP; j++) if (j == jw) val[j] = -FLT_MAX;
        }
        wsel[rr] = w;
        isel[rr] = be;
    }
    float m9 = -FLT_MAX;
#pragma unroll
    for (int j = 0; j < NGRP; j++) m9 = fmaxf(m9, val[j]);
#pragma unroll
    for (int off = 16; off > 0; off >>= 1)
        m9 = fmaxf(m9, __shfl_xor_sync(FULL, m9, off));
    dirty |= (prev - m9) < EPS_DIRTY;

    float s = 0.0f;
#pragma unroll
    for (int rr = 0; rr < TOPKN; rr++) s = __fadd_rn(s, wsel[rr]);

    if (l == 0) {
        float* ow = out + (size_t)t * TOPKN;
        float* oi = out + (size_t)TTOT * TOPKN + (size_t)t * TOPKN;
#pragma unroll
        for (int rr = 0; rr < TOPKN; rr++) {
            ow[rr] = __fmul_rn(__fdiv_rn(wsel[rr], s), 2.5f);
            oi[rr] = (float)isel[rr];
        }
        if (dirty) {
            int slot = atomicAdd(&g_ndirty, 1);
            g_dirty[slot] = t;
        }
    }
}

// ---------------------------------------------------------------------------
// Exact routing helper (r7 semantics — 2-ulp tie window). DO NOT change.
// ---------------------------------------------------------------------------
__device__ __forceinline__ void route_one_exact(const float* __restrict__ lgp,
                                                const float* __restrict__ bias,
                                                float* __restrict__ out, int t, int l) {
    const unsigned FULL = 0xffffffffu;
    float orig[NGRP], val[NGRP], gscore[NGRP];
#pragma unroll
    for (int j = 0; j < NGRP; j++) {
        float s = xla_sigmoid(lgp[j * GSIZE + l]);
        orig[j] = s;
        val[j] = __fadd_rn(s, bias[j * GSIZE + l]);
    }
#pragma unroll
    for (int j = 0; j < NGRP; j++) {
        float m1 = val[j], m2 = -FLT_MAX;
#pragma unroll
        for (int off = 16; off > 0; off >>= 1) {
            float o1 = __shfl_xor_sync(FULL, m1, off);
            float o2 = __shfl_xor_sync(FULL, m2, off);
            float hi = fmaxf(m1, o1);
            float lo = fminf(m1, o1);
            m2 = fmaxf(fmaxf(m2, o2), lo);
            m1 = hi;
        }
        gscore[j] = __fadd_rn(m1, m2);
    }
    unsigned gsel = 0;
    for (int rr = 0; rr < TOPG; rr++) {
        float best = -FLT_MAX; int bi = 0;
#pragma unroll
        for (int j = 0; j < NGRP; j++)
            if (!((gsel >> j) & 1u) && gscore[j] > best) { best = gscore[j]; bi = j; }
        gsel |= 1u << bi;
    }
#pragma unroll
    for (int j = 0; j < NGRP; j++)
        if (!((gsel >> j) & 1u)) val[j] = -FLT_MAX;

    float wsel[TOPKN]; int isel[TOPKN];
#pragma unroll
    for (int rr = 0; rr < TOPKN; rr++) {
        float m = -FLT_MAX;
#pragma unroll
        for (int j = 0; j < NGRP; j++) m = fmaxf(m, val[j]);
#pragma unroll
        for (int off = 16; off > 0; off >>= 1)
            m = fmaxf(m, __shfl_xor_sync(FULL, m, off));
        float thr = m - fabsf(m) * 2.4e-7f;
        int cidx = 0x7fffffff;
#pragma unroll
        for (int j = 0; j < NGRP; j++)
            if (val[j] >= thr && cidx == 0x7fffffff) cidx = j * GSIZE + l;
#pragma unroll
        for (int off = 16; off > 0; off >>= 1)
            cidx = min(cidx, __shfl_xor_sync(FULL, cidx, off));
        int jw = cidx >> 5, lw = cidx & 31;
        float cand = 0.0f;
#pragma unroll
        for (int j = 0; j < NGRP; j++) if (j == jw) cand = orig[j];
        float w = __shfl_sync(FULL, cand, lw);
        if (l == lw) {
#pragma unroll
            for (int j = 0; j < NGRP; j++) if (j == jw) val[j] = -FLT_MAX;
        }
        wsel[rr] = w;
        isel[rr] = cidx;
    }
    float s = 0.0f;
#pragma unroll
    for (int rr = 0; rr < TOPKN; rr++) s = __fadd_rn(s, wsel[rr]);
    if (l == 0) {
        float* ow = out + (size_t)t * TOPKN;
        float* oi = out + (size_t)TTOT * TOPKN + (size_t)t * TOPKN;
#pragma unroll
        for (int rr = 0; rr < TOPKN; rr++) {
            ow[rr] = __fmul_rn(__fdiv_rn(wsel[rr], s), 2.5f);
            oi[rr] = (float)isel[rr];
        }
    }
}

// ---------------------------------------------------------------------------
// Exact recompute for dirty tokens. 512 threads: half0 (tid<256) computes
// tokens 0-2, half1 tokens 3-4 over shared smem-staged W. Each (token,
// expert) keeps the exact ascending-k single-accumulator IEEE-FMA chain.
// ---------------------------------------------------------------------------
__global__ __launch_bounds__(512) void route_exact(const float* __restrict__ X,
                                                   const float* __restrict__ W,
                                                   const float* __restrict__ bias,
                                                   float* __restrict__ out) {
    __shared__ float Ws[256][36];
    __shared__ float xs[RT_TOK][KC];
    __shared__ float slog[RT_TOK][NEXP];
    __shared__ int stok[RT_TOK];
    const int tid = threadIdx.x;
    const int etid = tid & 255;
    const int half = tid >> 8;
    const int nd = g_ndirty;
    // W loader: each of 512 threads stages 4 float4 = 16 floats (half a row)
    const int wrow = tid >> 1;
    const int woff = (tid & 1) * 16;

    for (int base = blockIdx.x * RT_TOK; base < nd; base += gridDim.x * RT_TOK) {
        __syncthreads();
        if (tid < RT_TOK) stok[tid] = g_dirty[min(base + tid, nd - 1)];
        __syncthreads();

        float a0 = 0.f, a1 = 0.f, a2 = 0.f;

        float4 wpre[4];
#pragma unroll
        for (int q = 0; q < 4; q++)
            wpre[q] = *(const float4*)(W + (size_t)wrow * KDIM + woff + q * 4);
        float xpre = (tid < RT_TOK * KC)
                         ? X[(size_t)stok[tid >> 5] * KDIM + (tid & 31)] : 0.f;

        for (int k0 = 0; k0 < KDIM; k0 += KC) {
#pragma unroll
            for (int q = 0; q < 4; q++)
                *(float4*)&Ws[wrow][woff + q * 4] = wpre[q];
            if (tid < RT_TOK * KC) xs[tid >> 5][tid & 31] = xpre;
            __syncthreads();

            if (k0 + KC < KDIM) {
#pragma unroll
                for (int q = 0; q < 4; q++)
                    wpre[q] = *(const float4*)(W + (size_t)wrow * KDIM
                                               + k0 + KC + woff + q * 4);
                if (tid < RT_TOK * KC)
                    xpre = X[(size_t)stok[tid >> 5] * KDIM + k0 + KC + (tid & 31)];
            }

            if (half == 0) {
#pragma unroll
                for (int kk = 0; kk < KC; kk += 4) {
                    float4 wv = *(const float4*)&Ws[etid][kk];
                    float4 v0 = *(const float4*)&xs[0][kk];
                    float4 v1 = *(const float4*)&xs[1][kk];
                    float4 v2 = *(const float4*)&xs[2][kk];
                    a0 = __fmaf_rn(v0.x, wv.x, a0); a0 = __fmaf_rn(v0.y, wv.y, a0);
                    a0 = __fmaf_rn(v0.z, wv.z, a0); a0 = __fmaf_rn(v0.w, wv.w, a0);
                    a1 = __fmaf_rn(v1.x, wv.x, a1); a1 = __fmaf_rn(v1.y, wv.y, a1);
                    a1 = __fmaf_rn(v1.z, wv.z, a1); a1 = __fmaf_rn(v1.w, wv.w, a1);
                    a2 = __fmaf_rn(v2.x, wv.x, a2); a2 = __fmaf_rn(v2.y, wv.y, a2);
                    a2 = __fmaf_rn(v2.z, wv.z, a2); a2 = __fmaf_rn(v2.w, wv.w, a2);
                }
            } else {
#pragma unroll
                for (int kk = 0; kk < KC; kk += 4) {
                    float4 wv = *(const float4*)&Ws[etid][kk];
                    float4 v0 = *(const float4*)&xs[3][kk];
                    float4 v1 = *(const float4*)&xs[4][kk];
                    a0 = __fmaf_rn(v0.x, wv.x, a0); a0 = __fmaf_rn(v0.y, wv.y, a0);
                    a0 = __fmaf_rn(v0.z, wv.z, a0); a0 = __fmaf_rn(v0.w, wv.w, a0);
                    a1 = __fmaf_rn(v1.x, wv.x, a1); a1 = __fmaf_rn(v1.y, wv.y, a1);
                    a1 = __fmaf_rn(v1.z, wv.z, a1); a1 = __fmaf_rn(v1.w, wv.w, a1);
                }
            }
            __syncthreads();
        }

        if (half == 0) {
            slog[0][etid] = a0; slog[1][etid] = a1; slog[2][etid] = a2;
        } else {
            slog[3][etid] = a0; slog[4][etid] = a1;
        }
        __syncthreads();
        int wid = tid >> 5;
        if (wid < RT_TOK && base + wid < nd)
            route_one_exact(slog[wid], bias, out, stok[wid], tid & 31);
    }
}

// ---------------------------------------------------------------------------
// ce counts from FINAL indices (after exact overwrite).
// ---------------------------------------------------------------------------
__global__ void count_kernel(const float* __restrict__ out) {
    int t = blockIdx.x * blockDim.x + threadIdx.x;
    if (t >= TTOT) return;
    int b = t >> 12;
    const float* oi = out + (size_t)TTOT * TOPKN + (size_t)t * TOPKN;
#pragma unroll
    for (int rr = 0; rr < TOPKN; rr++)
        atomicAdd(&g_counts[b * NEXP + (int)oi[rr]], 1.0f);
}

__global__ __launch_bounds__(256) void ssum_kernel() {
    int row0 = blockIdx.x * 16;
    int b = row0 / SEQ;
    int e = threadIdx.x;
    float s = 0.0f;
#pragma unroll 8
    for (int rr = 0; rr < 16; rr++)
        s += xla_sigmoid(g_logits[(size_t)(row0 + rr) * NEXP + e]);
    atomicAdd(&g_ssum[b * NEXP + e], s);
}

__global__ void aux_kernel(float* __restrict__ out) {
    __shared__ float red[512];
    int i = threadIdx.x;
    float term = (g_counts[i] * (1.0f / 128.0f)) * (g_ssum[i] * (1.0f / 4096.0f));
    red[i] = term;
    __syncthreads();
    for (int st = 256; st > 0; st >>= 1) {
        if (i < st) red[i] += red[i + st];
        __syncthreads();
    }
    if (i == 0) out[2 * TTOT * TOPKN] = red[0] * 0.5f * 0.001f;
}

extern "C" void kernel_launch(void* const* d_in, const int* in_sizes, int n_in,
                              void* d_out, int out_size) {
    const float* x    = (const float*)d_in[0];   // [2,4096,7168] fp32
    const float* w    = (const float*)d_in[1];   // [256,7168] fp32
    const float* bias = (const float*)d_in[2];   // [256] fp32
    float* out = (float*)d_out;

    zero_kernel<<<1, 512>>>();
    dim3 ggrid(NEXP / 128, TTOT / 128);
    gemm_bf16<<<ggrid, 256>>>(x, w);
    route_approx<<<TTOT / 8, 256>>>(bias, out);
    route_exact<<<148, 512>>>(x, w, bias, out);
    count_kernel<<<TTOT / 256, 256>>>(out);
    ssum_kernel<<<TTOT / 16, 256>>>();
    aux_kernel<<<1, 512>>>(out);
}

// round 17
// speedup vs baseline: 1.2104x; 1.2104x over previous
#include <cuda_runtime.h>
#include <cuda_bf16.h>
#include <math.h>
#include <float.h>
#include <stdint.h>

#define KDIM 7168
#define NEXP 256
#define NGRP 8
#define GSIZE 32
#define TOPKN 8
#define TOPG 4
#define TTOT 8192
#define BSZ 2
#define SEQ 4096

#define EPS_DIRTY 3.0e-5f
#define RT_TOK 5
#define KC 32

// Scratch (no cudaMalloc allowed)
__device__ float g_logits[(size_t)TTOT * NEXP];   // 8 MB (approx, bf16x3)
__device__ float g_counts[BSZ * NEXP];
__device__ float g_ssum[BSZ * NEXP];
__device__ int   g_dirty[TTOT];
__device__ int   g_ndirty;

// ---------------------------------------------------------------------------
// XLA-style logistic: sigmoid(x) = 0.5 + 0.5 * tanh_xla(0.5 * x).
// ---------------------------------------------------------------------------
__device__ __forceinline__ float xla_sigmoid(float x) {
    float t  = __fmul_rn(0.5f, x);
    float tc = fminf(fmaxf(t, -7.90531110763549805f), 7.90531110763549805f);
    float x2 = __fmul_rn(tc, tc);
    float p = -2.76076847742355e-16f;
    p = __fadd_rn(__fmul_rn(p, x2),  2.00018790482477e-13f);
    p = __fadd_rn(__fmul_rn(p, x2), -8.60467152213735e-11f);
    p = __fadd_rn(__fmul_rn(p, x2),  5.12229709037114e-08f);
    p = __fadd_rn(__fmul_rn(p, x2),  1.48572235717979e-05f);
    p = __fadd_rn(__fmul_rn(p, x2),  6.37261928875436e-04f);
    p = __fadd_rn(__fmul_rn(p, x2),  4.89352455891786e-03f);
    p = __fmul_rn(p, tc);
    float q = 1.19825839466702e-06f;
    q = __fadd_rn(__fmul_rn(q, x2), 1.18534705686654e-04f);
    q = __fadd_rn(__fmul_rn(q, x2), 2.26843463243900e-03f);
    q = __fadd_rn(__fmul_rn(q, x2), 4.89352518554385e-03f);
    float th = __fdiv_rn(p, q);
    th = (fabsf(t) < 0.0004f) ? t : th;
    return __fadd_rn(0.5f, __fmul_rn(0.5f, th));
}

__global__ void zero_kernel() {
    int i = threadIdx.x;
    if (i < BSZ * NEXP) { g_counts[i] = 0.0f; g_ssum[i] = 0.0f; }
    if (i == 0) g_ndirty = 0;
}

// ---------------------------------------------------------------------------
// bf16 helpers
// ---------------------------------------------------------------------------
__device__ __forceinline__ void bsplit2(float x0, float x1,
                                        uint32_t& h, uint32_t& l) {
    __nv_bfloat16 h0 = __float2bfloat16_rn(x0);
    __nv_bfloat16 h1 = __float2bfloat16_rn(x1);
    h = ((uint32_t)__bfloat16_as_ushort(h1) << 16) | __bfloat16_as_ushort(h0);
    __nv_bfloat16 l0 = __float2bfloat16_rn(x0 - __bfloat162float(h0));
    __nv_bfloat16 l1 = __float2bfloat16_rn(x1 - __bfloat162float(h1));
    l = ((uint32_t)__bfloat16_as_ushort(l1) << 16) | __bfloat16_as_ushort(l0);
}
__device__ __forceinline__ void mmabf(float* c, const uint32_t* a, const uint32_t* b) {
    asm volatile(
        "mma.sync.aligned.m16n8k16.row.col.f32.bf16.bf16.f32 "
        "{%0,%1,%2,%3}, {%4,%5,%6,%7}, {%8,%9}, {%0,%1,%2,%3};"
        : "+f"(c[0]), "+f"(c[1]), "+f"(c[2]), "+f"(c[3])
        : "r"(a[0]), "r"(a[1]), "r"(a[2]), "r"(a[3]), "r"(b[0]), "r"(b[1]));
}
__device__ __forceinline__ uint32_t cvta_smem(const void* p) {
    uint32_t a;
    asm("{ .reg .u64 t; cvta.to.shared.u64 t, %1; cvt.u32.u64 %0, t; }"
        : "=r"(a) : "l"(p));
    return a;
}
__device__ __forceinline__ void ldm4(uint32_t& r0, uint32_t& r1,
                                     uint32_t& r2, uint32_t& r3, uint32_t a) {
    asm volatile("ldmatrix.sync.aligned.m8n8.x4.shared.b16 {%0,%1,%2,%3}, [%4];"
                 : "=r"(r0), "=r"(r1), "=r"(r2), "=r"(r3) : "r"(a));
}

// ---------------------------------------------------------------------------
// Approx GEMM: logits = x @ w^T via 3-pass bf16 split (hh + lh + hl).
// BM=BN=128, BK=32, 256 threads, warps 4(m) x 2(n), warp tile 32x64.
// Fragments via ldmatrix.x4 (validated bit-identical in r16).
// ---------------------------------------------------------------------------
__global__ __launch_bounds__(256) void gemm_bf16(const float* __restrict__ A,
                                                 const float* __restrict__ B) {
    __shared__ uint32_t Ah[128][20], Al[128][20];
    __shared__ uint32_t Bh[128][20], Bl[128][20];

    const int tid = threadIdx.x;
    const int l = tid & 31;
    const int wid = tid >> 5;
    const int warpm = wid & 3, warpn = wid >> 2;
    const int m0 = warpm * 32, n0 = warpn * 64;
    const int t0 = blockIdx.y * 128, e0 = blockIdx.x * 128;

    const int lm = tid >> 1;            // 0..127 (row)
    const int lhalf = (tid & 1) * 16;   // float offset within 32-k chunk
    const float* Aptr = A + (size_t)(t0 + lm) * KDIM + lhalf;
    const float* Bptr = B + (size_t)(e0 + lm) * KDIM + lhalf;

    float acc[2][8][4];
#pragma unroll
    for (int i = 0; i < 2; i++)
#pragma unroll
        for (int j = 0; j < 8; j++)
#pragma unroll
            for (int v = 0; v < 4; v++) acc[i][j][v] = 0.0f;

    float4 av[4], bv[4];
#pragma unroll
    for (int q = 0; q < 4; q++) {
        av[q] = *(const float4*)(Aptr + q * 4);
        bv[q] = *(const float4*)(Bptr + q * 4);
    }

    const int jbase = (tid & 1) * 8;
    const int g  = l >> 3;        // ldmatrix lane group 0..3
    const int r8 = l & 7;
    const uint32_t ah_base = cvta_smem(&Ah[0][0]);
    const uint32_t al_base = cvta_smem(&Al[0][0]);
    const uint32_t bh_base = cvta_smem(&Bh[0][0]);
    const uint32_t bl_base = cvta_smem(&Bl[0][0]);

    for (int k0 = 0; k0 < KDIM; k0 += 32) {
        __syncthreads();
#pragma unroll
        for (int q = 0; q < 4; q++) {
            uint32_t h, lo;
            bsplit2(av[q].x, av[q].y, h, lo);
            Ah[lm][jbase + q * 2] = h;     Al[lm][jbase + q * 2] = lo;
            bsplit2(av[q].z, av[q].w, h, lo);
            Ah[lm][jbase + q * 2 + 1] = h; Al[lm][jbase + q * 2 + 1] = lo;
            bsplit2(bv[q].x, bv[q].y, h, lo);
            Bh[lm][jbase + q * 2] = h;     Bl[lm][jbase + q * 2] = lo;
            bsplit2(bv[q].z, bv[q].w, h, lo);
            Bh[lm][jbase + q * 2 + 1] = h; Bl[lm][jbase + q * 2 + 1] = lo;
        }
        __syncthreads();
        if (k0 + 32 < KDIM) {
#pragma unroll
            for (int q = 0; q < 4; q++) {
                av[q] = *(const float4*)(Aptr + k0 + 32 + q * 4);
                bv[q] = *(const float4*)(Bptr + k0 + 32 + q * 4);
            }
        }

#pragma unroll
        for (int kb = 0; kb < 2; kb++) {
            const int joff = kb * 8;
            uint32_t afh[2][4], afl[2][4], bf[8][2];
#pragma unroll
            for (int mt = 0; mt < 2; mt++) {
                int arow = m0 + mt * 16 + r8 + (g & 1) * 8;
                int awrd = joff + (g >> 1) * 4;
                uint32_t off = (uint32_t)(arow * 20 + awrd) * 4u;
                ldm4(afh[mt][0], afh[mt][1], afh[mt][2], afh[mt][3], ah_base + off);
                ldm4(afl[mt][0], afl[mt][1], afl[mt][2], afl[mt][3], al_base + off);
            }
#pragma unroll
            for (int p = 0; p < 4; p++) {
                int brow = n0 + (p * 2 + (g >> 1)) * 8 + r8;
                int bwrd = joff + (g & 1) * 4;
                uint32_t off = (uint32_t)(brow * 20 + bwrd) * 4u;
                ldm4(bf[p * 2][0], bf[p * 2][1], bf[p * 2 + 1][0], bf[p * 2 + 1][1],
                     bh_base + off);
            }
#pragma unroll
            for (int mt = 0; mt < 2; mt++)
#pragma unroll
                for (int nt = 0; nt < 8; nt++) mmabf(acc[mt][nt], afh[mt], bf[nt]);
#pragma unroll
            for (int mt = 0; mt < 2; mt++)
#pragma unroll
                for (int nt = 0; nt < 8; nt++) mmabf(acc[mt][nt], afl[mt], bf[nt]);
#pragma unroll
            for (int p = 0; p < 4; p++) {
                int brow = n0 + (p * 2 + (g >> 1)) * 8 + r8;
                int bwrd = joff + (g & 1) * 4;
                uint32_t off = (uint32_t)(brow * 20 + bwrd) * 4u;
                ldm4(bf[p * 2][0], bf[p * 2][1], bf[p * 2 + 1][0], bf[p * 2 + 1][1],
                     bl_base + off);
            }
#pragma unroll
            for (int mt = 0; mt < 2; mt++)
#pragma unroll
                for (int nt = 0; nt < 8; nt++) mmabf(acc[mt][nt], afh[mt], bf[nt]);
        }
    }

    const int r = l >> 2, c = l & 3;
#pragma unroll
    for (int mt = 0; mt < 2; mt++)
#pragma unroll
        for (int nt = 0; nt < 8; nt++) {
            int row = t0 + m0 + mt * 16 + r;
            int col = e0 + n0 + nt * 8 + 2 * c;
            *(float2*)&g_logits[(size_t)row * NEXP + col] =
                make_float2(acc[mt][nt][0], acc[mt][nt][1]);
            *(float2*)&g_logits[(size_t)(row + 8) * NEXP + col] =
                make_float2(acc[mt][nt][2], acc[mt][nt][3]);
        }
}

// ---------------------------------------------------------------------------
// Approx routing + dirty detection (validated r11-r16).
// ---------------------------------------------------------------------------
__global__ __launch_bounds__(256) void route_approx(const float* __restrict__ bias,
                                                    float* __restrict__ out) {
    const unsigned FULL = 0xffffffffu;
    int warp = (blockIdx.x * blockDim.x + threadIdx.x) >> 5;
    int l = threadIdx.x & 31;
    if (warp >= TTOT) return;
    const int t = warp;
    const float* lgp = g_logits + (size_t)t * NEXP;

    float orig[NGRP], val[NGRP], gscore[NGRP];
#pragma unroll
    for (int j = 0; j < NGRP; j++) {
        float s = xla_sigmoid(lgp[j * GSIZE + l]);
        orig[j] = s;
        val[j] = __fadd_rn(s, bias[j * GSIZE + l]);
    }

#pragma unroll
    for (int j = 0; j < NGRP; j++) {
        float m1 = val[j], m2 = -FLT_MAX;
#pragma unroll
        for (int off = 16; off > 0; off >>= 1) {
            float o1 = __shfl_xor_sync(FULL, m1, off);
            float o2 = __shfl_xor_sync(FULL, m2, off);
            float hi = fmaxf(m1, o1);
            float lo = fminf(m1, o1);
            m2 = fmaxf(fmaxf(m2, o2), lo);
            m1 = hi;
        }
        gscore[j] = __fadd_rn(m1, m2);
    }

    unsigned gsel = 0; float g4 = 0.0f;
    for (int rr = 0; rr < TOPG; rr++) {
        float best = -FLT_MAX; int bi = 0;
#pragma unroll
        for (int j = 0; j < NGRP; j++)
            if (!((gsel >> j) & 1u) && gscore[j] > best) { best = gscore[j]; bi = j; }
        gsel |= 1u << bi;
        g4 = best;
    }
    float g5 = -FLT_MAX;
#pragma unroll
    for (int j = 0; j < NGRP; j++)
        if (!((gsel >> j) & 1u)) g5 = fmaxf(g5, gscore[j]);
    bool dirty = (g4 - g5) < EPS_DIRTY;

#pragma unroll
    for (int j = 0; j < NGRP; j++)
        if (!((gsel >> j) & 1u)) val[j] = -FLT_MAX;

    float wsel[TOPKN]; int isel[TOPKN];
    float prev = 1e30f;
#pragma unroll
    for (int rr = 0; rr < TOPKN; rr++) {
        float bv = -FLT_MAX; int bj = 0;
#pragma unroll
        for (int j = 0; j < NGRP; j++)
            if (val[j] > bv) { bv = val[j]; bj = j; }
        int be = bj * GSIZE + l;
#pragma unroll
        for (int off = 16; off > 0; off >>= 1) {
            float ov = __shfl_xor_sync(FULL, bv, off);
            int   oe = __shfl_xor_sync(FULL, be, off);
            if (ov > bv || (ov == bv && oe < be)) { bv = ov; be = oe; }
        }
        dirty |= (prev - bv) < EPS_DIRTY;
        prev = bv;
        int jw = be >> 5, lw = be & 31;
        float cand = 0.0f;
#pragma unroll
        for (int j = 0; j < NGRP; j++) if (j == jw) cand = orig[j];
        float w = __shfl_sync(FULL, cand, lw);
        if (l == lw) {
#pragma unroll
            for (int j = 0; j < NGRP; j++) if (j == jw) val[j] = -FLT_MAX;
        }
        wsel[rr] = w;
        isel[rr] = be;
    }
    float m9 = -FLT_MAX;
#pragma unroll
    for (int j = 0; j < NGRP; j++) m9 = fmaxf(m9, val[j]);
#pragma unroll
    for (int off = 16; off > 0; off >>= 1)
        m9 = fmaxf(m9, __shfl_xor_sync(FULL, m9, off));
    dirty |= (prev - m9) < EPS_DIRTY;

    float s = 0.0f;
#pragma unroll
    for (int rr = 0; rr < TOPKN; rr++) s = __fadd_rn(s, wsel[rr]);

    if (l == 0) {
        float* ow = out + (size_t)t * TOPKN;
        float* oi = out + (size_t)TTOT * TOPKN + (size_t)t * TOPKN;
#pragma unroll
        for (int rr = 0; rr < TOPKN; rr++) {
            ow[rr] = __fmul_rn(__fdiv_rn(wsel[rr], s), 2.5f);
            oi[rr] = (float)isel[rr];
        }
        if (dirty) {
            int slot = atomicAdd(&g_ndirty, 1);
            g_dirty[slot] = t;
        }
    }
}

// ---------------------------------------------------------------------------
// Exact routing helper (r7 semantics — 2-ulp tie window). DO NOT change.
// ---------------------------------------------------------------------------
__device__ __forceinline__ void route_one_exact(const float* __restrict__ lgp,
                                                const float* __restrict__ bias,
                                                float* __restrict__ out, int t, int l) {
    const unsigned FULL = 0xffffffffu;
    float orig[NGRP], val[NGRP], gscore[NGRP];
#pragma unroll
    for (int j = 0; j < NGRP; j++) {
        float s = xla_sigmoid(lgp[j * GSIZE + l]);
        orig[j] = s;
        val[j] = __fadd_rn(s, bias[j * GSIZE + l]);
    }
#pragma unroll
    for (int j = 0; j < NGRP; j++) {
        float m1 = val[j], m2 = -FLT_MAX;
#pragma unroll
        for (int off = 16; off > 0; off >>= 1) {
            float o1 = __shfl_xor_sync(FULL, m1, off);
            float o2 = __shfl_xor_sync(FULL, m2, off);
            float hi = fmaxf(m1, o1);
            float lo = fminf(m1, o1);
            m2 = fmaxf(fmaxf(m2, o2), lo);
            m1 = hi;
        }
        gscore[j] = __fadd_rn(m1, m2);
    }
    unsigned gsel = 0;
    for (int rr = 0; rr < TOPG; rr++) {
        float best = -FLT_MAX; int bi = 0;
#pragma unroll
        for (int j = 0; j < NGRP; j++)
            if (!((gsel >> j) & 1u) && gscore[j] > best) { best = gscore[j]; bi = j; }
        gsel |= 1u << bi;
    }
#pragma unroll
    for (int j = 0; j < NGRP; j++)
        if (!((gsel >> j) & 1u)) val[j] = -FLT_MAX;

    float wsel[TOPKN]; int isel[TOPKN];
#pragma unroll
    for (int rr = 0; rr < TOPKN; rr++) {
        float m = -FLT_MAX;
#pragma unroll
        for (int j = 0; j < NGRP; j++) m = fmaxf(m, val[j]);
#pragma unroll
        for (int off = 16; off > 0; off >>= 1)
            m = fmaxf(m, __shfl_xor_sync(FULL, m, off));
        float thr = m - fabsf(m) * 2.4e-7f;
        int cidx = 0x7fffffff;
#pragma unroll
        for (int j = 0; j < NGRP; j++)
            if (val[j] >= thr && cidx == 0x7fffffff) cidx = j * GSIZE + l;
#pragma unroll
        for (int off = 16; off > 0; off >>= 1)
            cidx = min(cidx, __shfl_xor_sync(FULL, cidx, off));
        int jw = cidx >> 5, lw = cidx & 31;
        float cand = 0.0f;
#pragma unroll
        for (int j = 0; j < NGRP; j++) if (j == jw) cand = orig[j];
        float w = __shfl_sync(FULL, cand, lw);
        if (l == lw) {
#pragma unroll
            for (int j = 0; j < NGRP; j++) if (j == jw) val[j] = -FLT_MAX;
        }
        wsel[rr] = w;
        isel[rr] = cidx;
    }
    float s = 0.0f;
#pragma unroll
    for (int rr = 0; rr < TOPKN; rr++) s = __fadd_rn(s, wsel[rr]);
    if (l == 0) {
        float* ow = out + (size_t)t * TOPKN;
        float* oi = out + (size_t)TTOT * TOPKN + (size_t)t * TOPKN;
#pragma unroll
        for (int rr = 0; rr < TOPKN; rr++) {
            ow[rr] = __fmul_rn(__fdiv_rn(wsel[rr], s), 2.5f);
            oi[rr] = (float)isel[rr];
        }
    }
}

// ---------------------------------------------------------------------------
// Exact recompute for dirty tokens — r15 version (measured 219 us).
// 256 threads, smem-staged W, RT_TOK=5. Exact ascending-k single-accumulator
// IEEE-FMA chain per (token, expert).
// ---------------------------------------------------------------------------
__global__ __launch_bounds__(256) void route_exact(const float* __restrict__ X,
                                                   const float* __restrict__ W,
                                                   const float* __restrict__ bias,
                                                   float* __restrict__ out) {
    __shared__ float Ws[256][36];
    __shared__ float xs[RT_TOK][KC];
    __shared__ float slog[RT_TOK][NEXP];
    __shared__ int stok[RT_TOK];
    const int tid = threadIdx.x;
    const int nd = g_ndirty;          // route_approx completed (stream order)
    const int er = tid >> 3;          // 0..31
    const int k4 = (tid & 7) * 4;     // float4 column

    for (int base = blockIdx.x * RT_TOK; base < nd; base += gridDim.x * RT_TOK) {
        __syncthreads();
        if (tid < RT_TOK) stok[tid] = g_dirty[min(base + tid, nd - 1)];
        __syncthreads();

        float a0 = 0.f, a1 = 0.f, a2 = 0.f, a3 = 0.f, a4 = 0.f;

        float4 wpre[8];
#pragma unroll
        for (int j = 0; j < 8; j++)
            wpre[j] = *(const float4*)(W + (size_t)(j * 32 + er) * KDIM + k4);
        float xpre = (tid < RT_TOK * KC)
                         ? X[(size_t)stok[tid >> 5] * KDIM + (tid & 31)] : 0.f;

        for (int k0 = 0; k0 < KDIM; k0 += KC) {
#pragma unroll
            for (int j = 0; j < 8; j++)
                *(float4*)&Ws[j * 32 + er][k4] = wpre[j];
            if (tid < RT_TOK * KC) xs[tid >> 5][tid & 31] = xpre;
            __syncthreads();

            if (k0 + KC < KDIM) {
#pragma unroll
                for (int j = 0; j < 8; j++)
                    wpre[j] = *(const float4*)(W + (size_t)(j * 32 + er) * KDIM
                                               + k0 + KC + k4);
                if (tid < RT_TOK * KC)
                    xpre = X[(size_t)stok[tid >> 5] * KDIM + k0 + KC + (tid & 31)];
            }

#pragma unroll
            for (int kk = 0; kk < KC; kk += 4) {
                float4 wv = *(const float4*)&Ws[tid][kk];
                float4 v0 = *(const float4*)&xs[0][kk];
                float4 v1 = *(const float4*)&xs[1][kk];
                float4 v2 = *(const float4*)&xs[2][kk];
                float4 v3 = *(const float4*)&xs[3][kk];
                float4 v4 = *(const float4*)&xs[4][kk];
                a0 = __fmaf_rn(v0.x, wv.x, a0); a0 = __fmaf_rn(v0.y, wv.y, a0);
                a0 = __fmaf_rn(v0.z, wv.z, a0); a0 = __fmaf_rn(v0.w, wv.w, a0);
                a1 = __fmaf_rn(v1.x, wv.x, a1); a1 = __fmaf_rn(v1.y, wv.y, a1);
                a1 = __fmaf_rn(v1.z, wv.z, a1); a1 = __fmaf_rn(v1.w, wv.w, a1);
                a2 = __fmaf_rn(v2.x, wv.x, a2); a2 = __fmaf_rn(v2.y, wv.y, a2);
                a2 = __fmaf_rn(v2.z, wv.z, a2); a2 = __fmaf_rn(v2.w, wv.w, a2);
                a3 = __fmaf_rn(v3.x, wv.x, a3); a3 = __fmaf_rn(v3.y, wv.y, a3);
                a3 = __fmaf_rn(v3.z, wv.z, a3); a3 = __fmaf_rn(v3.w, wv.w, a3);
                a4 = __fmaf_rn(v4.x, wv.x, a4); a4 = __fmaf_rn(v4.y, wv.y, a4);
                a4 = __fmaf_rn(v4.z, wv.z, a4); a4 = __fmaf_rn(v4.w, wv.w, a4);
            }
            __syncthreads();
        }

        slog[0][tid] = a0; slog[1][tid] = a1; slog[2][tid] = a2;
        slog[3][tid] = a3; slog[4][tid] = a4;
        __syncthreads();
        int wid = tid >> 5;
        if (wid < RT_TOK && base + wid < nd)
            route_one_exact(slog[wid], bias, out, stok[wid], tid & 31);
    }
}

// ---------------------------------------------------------------------------
// ce counts from FINAL indices (after exact overwrite).
// ---------------------------------------------------------------------------
__global__ void count_kernel(const float* __restrict__ out) {
    int t = blockIdx.x * blockDim.x + threadIdx.x;
    if (t >= TTOT) return;
    int b = t >> 12;
    const float* oi = out + (size_t)TTOT * TOPKN + (size_t)t * TOPKN;
#pragma unroll
    for (int rr = 0; rr < TOPKN; rr++)
        atomicAdd(&g_counts[b * NEXP + (int)oi[rr]], 1.0f);
}

__global__ __launch_bounds__(256) void ssum_kernel() {
    int row0 = blockIdx.x * 16;
    int b = row0 / SEQ;
    int e = threadIdx.x;
    float s = 0.0f;
#pragma unroll 8
    for (int rr = 0; rr < 16; rr++)
        s += xla_sigmoid(g_logits[(size_t)(row0 + rr) * NEXP + e]);
    atomicAdd(&g_ssum[b * NEXP + e], s);
}

__global__ void aux_kernel(float* __restrict__ out) {
    __shared__ float red[512];
    int i = threadIdx.x;
    float term = (g_counts[i] * (1.0f / 128.0f)) * (g_ssum[i] * (1.0f / 4096.0f));
    red[i] = term;
    __syncthreads();
    for (int st = 256; st > 0; st >>= 1) {
        if (i < st) red[i] += red[i + st];
        __syncthreads();
    }
    if (i == 0) out[2 * TTOT * TOPKN] = red[0] * 0.5f * 0.001f;
}

extern "C" void kernel_launch(void* const* d_in, const int* in_sizes, int n_in,
                              void* d_out, int out_size) {
    const float* x    = (const float*)d_in[0];   // [2,4096,7168] fp32
    const float* w    = (const float*)d_in[1];   // [256,7168] fp32
    const float* bias = (const float*)d_in[2];   // [256] fp32
    float* out = (float*)d_out;

    zero_kernel<<<1, 512>>>();
    dim3 ggrid(NEXP / 128, TTOT / 128);
    gemm_bf16<<<ggrid, 256>>>(x, w);
    route_approx<<<TTOT / 8, 256>>>(bias, out);
    route_exact<<<148, 256>>>(x, w, bias, out);
    count_kernel<<<TTOT / 256, 256>>>(out);
    ssum_kernel<<<TTOT / 16, 256>>>();
    aux_kernel<<<1, 512>>>(out);
}